// round 16
// baseline (speedup 1.0000x reference)
#include <cuda_runtime.h>

// LSTM autoencoder: B=4096, T=512, F=8, H=16.
// One 16-lane group per batch element (2 per warp). Lane q owns h[q], c[q] and
// gate rows {q, 16+q, 32+q, 48+q} (i,f,g,o). Recurrent/input/output GEMVs done
// with packed fma.rn.f32x2 on register-resident weights; h broadcast via
// width-16 warp shuffles.

#define Bn 4096
#define Tn 512
#define Fn 8
#define Hn 16

__device__ __forceinline__ float ex2f(float x) {
    float r; asm("ex2.approx.ftz.f32 %0, %1;" : "=f"(r) : "f"(x)); return r;
}
__device__ __forceinline__ float rcpf(float x) {
    float r; asm("rcp.approx.ftz.f32 %0, %1;" : "=f"(r) : "f"(x)); return r;
}
__device__ __forceinline__ float sigf(float x) {
    // 1 / (1 + 2^(-x*log2e))
    return rcpf(1.0f + ex2f(-1.4426950408889634f * x));
}
__device__ __forceinline__ float tanhf_fast(float x) {
    // (1 - e) / (1 + e), e = 2^(-2x*log2e); clamp avoids inf -> NaN
    x = fminf(fmaxf(x, -10.0f), 10.0f);
    float e = ex2f(-2.8853900817779268f * x);
    return (1.0f - e) * rcpf(1.0f + e);
}

// Packed f32x2 helpers (carried in a .b64 "double" register pair)
__device__ __forceinline__ double pk2(float lo, float hi) {
    double d; asm("mov.b64 %0, {%1, %2};" : "=d"(d) : "f"(lo), "f"(hi)); return d;
}
__device__ __forceinline__ void up2(double d, float& lo, float& hi) {
    asm("mov.b64 {%0, %1}, %2;" : "=f"(lo), "=f"(hi) : "d"(d));
}
__device__ __forceinline__ double ffma2(double a, double b, double c) {
    double r; asm("fma.rn.f32x2 %0, %1, %2, %3;" : "=d"(r) : "d"(a), "d"(b), "d"(c));
    return r;
}

__global__ void __launch_bounds__(64, 8)
lstm_ae_kernel(const float* __restrict__ x,
               const float* __restrict__ eWih, const float* __restrict__ eWhh,
               const float* __restrict__ ebih, const float* __restrict__ ebhh,
               const float* __restrict__ dWih, const float* __restrict__ dWhh,
               const float* __restrict__ dbih, const float* __restrict__ dbhh,
               const float* __restrict__ oW,   const float* __restrict__ obv,
               float* __restrict__ out)
{
    const unsigned FULL = 0xffffffffu;
    const int gwarp = (blockIdx.x * blockDim.x + threadIdx.x) >> 5;
    const int lane  = threadIdx.x & 31;
    const int q     = lane & 15;              // lane within 16-lane group
    const int b     = gwarp * 2 + (lane >> 4);  // batch element

    // ---------------- encoder weights (registers, packed pairs) --------------
    double whh_if[Hn], whh_go[Hn];
#pragma unroll
    for (int k = 0; k < Hn; k++) {
        whh_if[k] = pk2(eWhh[q * Hn + k],            eWhh[(Hn + q) * Hn + k]);
        whh_go[k] = pk2(eWhh[(2 * Hn + q) * Hn + k], eWhh[(3 * Hn + q) * Hn + k]);
    }
    double wih_if[Fn], wih_go[Fn];
#pragma unroll
    for (int f = 0; f < Fn; f++) {
        wih_if[f] = pk2(eWih[q * Fn + f],            eWih[(Hn + q) * Fn + f]);
        wih_go[f] = pk2(eWih[(2 * Hn + q) * Fn + f], eWih[(3 * Hn + q) * Fn + f]);
    }
    const double bias_if = pk2(ebih[q] + ebhh[q],
                               ebih[Hn + q] + ebhh[Hn + q]);
    const double bias_go = pk2(ebih[2 * Hn + q] + ebhh[2 * Hn + q],
                               ebih[3 * Hn + q] + ebhh[3 * Hn + q]);

    // ---------------- encoder recurrence -------------------------------------
    const float* xb = x + (size_t)b * (Tn * Fn);
    float h = 0.0f, c = 0.0f;
    float xv = xb[q & 7];                     // prefetch t=0 (coalesced 32B/group)

    for (int t = 0; t < Tn; t++) {
        const float xcur = xv;
        const int t1 = (t + 1 < Tn) ? t + 1 : t;
        xv = xb[t1 * Fn + (q & 7)];           // prefetch next step

        double aif = bias_if, ago = bias_go;
#pragma unroll
        for (int f = 0; f < Fn; f++) {
            float xf = __shfl_sync(FULL, xcur, f, 16);
            double x2 = pk2(xf, xf);
            aif = ffma2(wih_if[f], x2, aif);
            ago = ffma2(wih_go[f], x2, ago);
        }
#pragma unroll
        for (int k = 0; k < Hn; k++) {
            float hk = __shfl_sync(FULL, h, k, 16);
            double h2 = pk2(hk, hk);
            aif = ffma2(whh_if[k], h2, aif);
            ago = ffma2(whh_go[k], h2, ago);
        }
        float gi, gf, gg, go;
        up2(aif, gi, gf);
        up2(ago, gg, go);
        gi = sigf(gi); gf = sigf(gf); gg = tanhf_fast(gg); go = sigf(go);
        c = gf * c + gi * gg;
        h = go * tanhf_fast(c);
    }
    const float hT = h;

    // ---------------- decoder weights + constant input projection ------------
#pragma unroll
    for (int k = 0; k < Hn; k++) {
        whh_if[k] = pk2(dWhh[q * Hn + k],            dWhh[(Hn + q) * Hn + k]);
        whh_go[k] = pk2(dWhh[(2 * Hn + q) * Hn + k], dWhh[(3 * Hn + q) * Hn + k]);
    }
    double xp_if = pk2(dbih[q] + dbhh[q],
                       dbih[Hn + q] + dbhh[Hn + q]);
    double xp_go = pk2(dbih[2 * Hn + q] + dbhh[2 * Hn + q],
                       dbih[3 * Hn + q] + dbhh[3 * Hn + q]);
#pragma unroll
    for (int k = 0; k < Hn; k++) {
        float hk = __shfl_sync(FULL, hT, k, 16);
        double h2 = pk2(hk, hk);
        xp_if = ffma2(pk2(dWih[q * Hn + k],            dWih[(Hn + q) * Hn + k]), h2, xp_if);
        xp_go = ffma2(pk2(dWih[(2 * Hn + q) * Hn + k], dWih[(3 * Hn + q) * Hn + k]), h2, xp_go);
    }

    // output projection weights: lane q<8 owns output feature q
    const int fo = q & 7;
    float wout[Hn];
#pragma unroll
    for (int k = 0; k < Hn; k++) wout[k] = oW[fo * Hn + k];
    const float outb = obv[fo];

    // ---------------- decoder recurrence (fused output projection) -----------
    float* op = out + (size_t)b * (Tn * Fn);
    h = 0.0f; c = 0.0f;
    for (int t = 0; t < Tn; t++) {
        double aif = xp_if, ago = xp_go;
        float oacc = outb;                    // out for decoded step t-1
#pragma unroll
        for (int k = 0; k < Hn; k++) {
            float hk = __shfl_sync(FULL, h, k, 16);   // h = h_{t-1}
            double h2 = pk2(hk, hk);
            aif = ffma2(whh_if[k], h2, aif);
            ago = ffma2(whh_go[k], h2, ago);
            oacc = fmaf(wout[k], hk, oacc);
        }
        if (t > 0 && q < 8) op[(t - 1) * Fn + q] = oacc;

        float gi, gf, gg, go;
        up2(aif, gi, gf);
        up2(ago, gg, go);
        gi = sigf(gi); gf = sigf(gf); gg = tanhf_fast(gg); go = sigf(go);
        c = gf * c + gi * gg;
        h = go * tanhf_fast(c);               // decoded[t]
    }
    // final timestep output (decoded[T-1])
    float oacc = outb;
#pragma unroll
    for (int k = 0; k < Hn; k++) {
        float hk = __shfl_sync(FULL, h, k, 16);
        oacc = fmaf(wout[k], hk, oacc);
    }
    if (q < 8) op[(Tn - 1) * Fn + q] = oacc;
}

extern "C" void kernel_launch(void* const* d_in, const int* in_sizes, int n_in,
                              void* d_out, int out_size)
{
    const float* x    = (const float*)d_in[0];
    const float* eWih = (const float*)d_in[1];
    const float* eWhh = (const float*)d_in[2];
    const float* ebih = (const float*)d_in[3];
    const float* ebhh = (const float*)d_in[4];
    const float* dWih = (const float*)d_in[5];
    const float* dWhh = (const float*)d_in[6];
    const float* dbih = (const float*)d_in[7];
    const float* dbhh = (const float*)d_in[8];
    const float* oW   = (const float*)d_in[9];
    const float* obv  = (const float*)d_in[10];
    float* out = (float*)d_out;

    // 4096 batches * 16 lanes = 65536 threads; 64-thread blocks -> 1024 blocks
    lstm_ae_kernel<<<1024, 64>>>(x, eWih, eWhh, ebih, ebhh,
                                 dWih, dWhh, dbih, dbhh, oW, obv, out);
}